// round 6
// baseline (speedup 1.0000x reference)
#include <cuda_runtime.h>
#include <cstdint>
#include <math.h>

// Problem constants
#define HW_   4096
#define C_IN_ 512
#define MMID_ 256
#define NB_   16

// Scratch (device globals: allocation-free, graph-capturable)
__device__ float g_state [NB_ * MMID_ * HW_];   // 64 MB
__device__ float g_proj  [NB_ * MMID_ * HW_];   // 64 MB
__device__ float g_attn  [NB_ * MMID_ * MMID_]; //  4 MB
__device__ float g_rstate[NB_ * MMID_ * HW_];   // 64 MB

__device__ __forceinline__ uint32_t f2tf32(float x) {
    uint32_t r;
    asm("cvt.rna.tf32.f32 %0, %1;" : "=r"(r) : "f"(x));
    return r;
}

__device__ __forceinline__ void mma_tf32(float c[4], const uint32_t a[4], const uint32_t b[2]) {
    asm volatile(
        "mma.sync.aligned.m16n8k8.row.col.f32.tf32.tf32.f32 "
        "{%0,%1,%2,%3}, {%4,%5,%6,%7}, {%8,%9}, {%0,%1,%2,%3};"
        : "+f"(c[0]), "+f"(c[1]), "+f"(c[2]), "+f"(c[3])
        : "r"(a[0]), "r"(a[1]), "r"(a[2]), "r"(a[3]),
          "r"(b[0]), "r"(b[1]));
}

__device__ __forceinline__ void cp16(uint32_t smem_dst, const void* gsrc) {
    asm volatile("cp.async.cg.shared.global [%0], [%1], 16;\n"
                 :: "r"(smem_dst), "l"(gsrc));
}
__device__ __forceinline__ void cp_commit() {
    asm volatile("cp.async.commit_group;\n");
}
template<int N>
__device__ __forceinline__ void cp_wait() {
    asm volatile("cp.async.wait_group %0;\n" :: "n"(N));
}

// ---------------------------------------------------------------------------
// Batched tf32 GEMM, 2-stage cp.async double-buffered smem pipeline.
// tf32 conversion is done ONCE per stage in smem (each thread converts the
// elements it cp.async'd itself: self-visible after wait_group, disjoint
// writes, published by the existing end-of-iter barrier). The compute phase
// then issues raw uint32 LDS only -> higher tensor-pipe issue fraction.
//   TRANS_B == false : B is [K,N] row-major       (C = A*B)
//   TRANS_B == true  : B is [N,K] row-major       (C = A*B^T)
// DUAL == true: gridDim.y doubled; upper half of y-blocks uses {A2,bias2,C2}.
// ---------------------------------------------------------------------------
template<int BM, int BN, int BK, int WM, int WN,
         bool TRANS_B, bool HAS_BIAS, bool HAS_RES, bool DUAL, int MINB>
__global__ void __launch_bounds__((BM / WM) * (BN / WN) * 32, MINB)
gemm_tf32_kernel(
    const float* __restrict__ A, long long strideA,
    const float* __restrict__ B, long long strideB,
    float*       __restrict__ Cout, long long strideC,
    const float* __restrict__ bias,
    const float* __restrict__ res, long long strideR,
    const float* __restrict__ A2,
    const float* __restrict__ bias2,
    float*       __restrict__ C2,
    int M, int N, int K, float alpha)
{
    constexpr int WARPS_M = BM / WM;
    constexpr int WARPS_N = BN / WN;
    constexpr int THREADS = WARPS_M * WARPS_N * 32;
    constexpr int MI = WM / 16;
    constexpr int NI = WN / 8;
    constexpr int LDA    = BK + 4;   // 36 : (row*36+k)%32 == row*4+k -> conflict-free
    constexpr int LDB_NN = BN + 8;   // 136/72 : (k*LDB+n)%32 == k*8+n -> conflict-free
    constexpr int B_ROWS = TRANS_B ? BN : BK;
    constexpr int B_LD   = TRANS_B ? LDA : LDB_NN;
    constexpr int A_ELEMS = BM * LDA;
    constexpr int B_ELEMS = B_ROWS * B_LD;
    constexpr int STAGE   = A_ELEMS + B_ELEMS;
    constexpr int A_F4 = (BM * BK / 4) / THREADS;
    constexpr int B_F4n = (BK * BN / 4) / THREADS;   // !TRANS_B count
    constexpr int B_F4t = (BM == BM) ? ((B_ROWS * BK / 4) / THREADS) : 0; // TRANS_B count
    static_assert((BM * BK / 4) % THREADS == 0, "");

    extern __shared__ float sm[];

    const int tid  = threadIdx.x;
    const int warp = tid >> 5;
    const int lane = tid & 31;
    const int wm   = warp / WARPS_N;
    const int wn   = warp % WARPS_N;
    const int g    = lane >> 2;
    const int tg   = lane & 3;
    const int batch = blockIdx.z;

    // ---- DUAL dispatch ----
    int by = blockIdx.y;
    const float* Asel = A;
    const float* bsel = bias;
    float*       Csel = Cout;
    if (DUAL) {
        const int halfY = gridDim.y >> 1;
        if (by >= halfY) { by -= halfY; Asel = A2; bsel = bias2; Csel = C2; }
    }

    const float* Ab = Asel + (size_t)batch * strideA + (size_t)by * BM * K;
    const float* Bb = B + (size_t)batch * strideB;

    // ---- async stage issue: gmem -> smem stage s (raw fp32) ----
    auto issue_stage = [&](int k0, int s) {
        float* sa = sm + s * STAGE;
        float* sb = sa + A_ELEMS;
        #pragma unroll
        for (int i = 0; i < A_F4; ++i) {
            int idx = tid + i * THREADS;
            int row = idx / (BK / 4);
            int c4  = (idx % (BK / 4)) * 4;
            cp16((uint32_t)__cvta_generic_to_shared(&sa[row * LDA + c4]),
                 Ab + (size_t)row * K + k0 + c4);
        }
        if (!TRANS_B) {
            const float* Bp = Bb + (size_t)k0 * N + (size_t)blockIdx.x * BN;
            #pragma unroll
            for (int i = 0; i < B_F4n; ++i) {
                int idx = tid + i * THREADS;
                int row = idx / (BN / 4);
                int c4  = (idx % (BN / 4)) * 4;
                cp16((uint32_t)__cvta_generic_to_shared(&sb[row * LDB_NN + c4]),
                     Bp + (size_t)row * N + c4);
            }
        } else {
            const float* Bp = Bb + (size_t)blockIdx.x * BN * K + k0;
            #pragma unroll
            for (int i = 0; i < B_F4t; ++i) {
                int idx = tid + i * THREADS;
                int row = idx / (BK / 4);
                int c4  = (idx % (BK / 4)) * 4;
                cp16((uint32_t)__cvta_generic_to_shared(&sb[row * LDA + c4]),
                     Bp + (size_t)row * K + c4);
            }
        }
    };

    // ---- per-stage tf32 conversion (each thread: exactly its own copies) ----
    auto convert_stage = [&](int s) {
        float* sa = sm + s * STAGE;
        float* sb = sa + A_ELEMS;
        #pragma unroll
        for (int i = 0; i < A_F4; ++i) {
            int idx = tid + i * THREADS;
            int row = idx / (BK / 4);
            int c4  = (idx % (BK / 4)) * 4;
            float4 v = *reinterpret_cast<const float4*>(&sa[row * LDA + c4]);
            uint4  u = make_uint4(f2tf32(v.x), f2tf32(v.y), f2tf32(v.z), f2tf32(v.w));
            *reinterpret_cast<uint4*>(&sa[row * LDA + c4]) = u;
        }
        if (!TRANS_B) {
            #pragma unroll
            for (int i = 0; i < B_F4n; ++i) {
                int idx = tid + i * THREADS;
                int row = idx / (BN / 4);
                int c4  = (idx % (BN / 4)) * 4;
                float4 v = *reinterpret_cast<const float4*>(&sb[row * LDB_NN + c4]);
                uint4  u = make_uint4(f2tf32(v.x), f2tf32(v.y), f2tf32(v.z), f2tf32(v.w));
                *reinterpret_cast<uint4*>(&sb[row * LDB_NN + c4]) = u;
            }
        } else {
            #pragma unroll
            for (int i = 0; i < B_F4t; ++i) {
                int idx = tid + i * THREADS;
                int row = idx / (BK / 4);
                int c4  = (idx % (BK / 4)) * 4;
                float4 v = *reinterpret_cast<const float4*>(&sb[row * LDA + c4]);
                uint4  u = make_uint4(f2tf32(v.x), f2tf32(v.y), f2tf32(v.z), f2tf32(v.w));
                *reinterpret_cast<uint4*>(&sb[row * LDA + c4]) = u;
            }
        }
    };

    float acc[MI][NI][4];
    #pragma unroll
    for (int mi = 0; mi < MI; ++mi)
        #pragma unroll
        for (int ni = 0; ni < NI; ++ni)
            #pragma unroll
            for (int j = 0; j < 4; ++j) acc[mi][ni][j] = 0.f;

    const int NT = K / BK;   // always >= 2 for our shapes

    // ---- prologue: stage tiles 0 and 1; convert tile 0 ----
    issue_stage(0, 0);  cp_commit();
    issue_stage(BK, 1); cp_commit();
    cp_wait<1>();        // stage 0 landed (raw)
    convert_stage(0);    // own elements only -> no barrier needed before
    __syncthreads();     // publish converted stage 0

    for (int it = 0; it < NT; ++it) {
        const int s = it & 1;
        const uint32_t* sa = reinterpret_cast<const uint32_t*>(sm + s * STAGE);
        const uint32_t* sb = sa + A_ELEMS;

        // ---- compute on stage s: BK/8 k-steps of m16n8k8 (raw uint32 LDS) ----
        #pragma unroll
        for (int ki = 0; ki < BK / 8; ++ki) {
            uint32_t afr[MI][4];
            uint32_t bfr[NI][2];
            #pragma unroll
            for (int mi = 0; mi < MI; ++mi) {
                int r = wm * WM + mi * 16;
                afr[mi][0] = sa[(r + g    ) * LDA + ki * 8 + tg    ];
                afr[mi][1] = sa[(r + 8 + g) * LDA + ki * 8 + tg    ];
                afr[mi][2] = sa[(r + g    ) * LDA + ki * 8 + 4 + tg];
                afr[mi][3] = sa[(r + 8 + g) * LDA + ki * 8 + 4 + tg];
            }
            #pragma unroll
            for (int ni = 0; ni < NI; ++ni) {
                int ncol = wn * WN + ni * 8 + g;
                if (!TRANS_B) {
                    bfr[ni][0] = sb[(ki * 8 + tg    ) * LDB_NN + ncol];
                    bfr[ni][1] = sb[(ki * 8 + 4 + tg) * LDB_NN + ncol];
                } else {
                    bfr[ni][0] = sb[ncol * LDA + ki * 8 + tg    ];
                    bfr[ni][1] = sb[ncol * LDA + ki * 8 + 4 + tg];
                }
            }
            #pragma unroll
            for (int mi = 0; mi < MI; ++mi)
                #pragma unroll
                for (int ni = 0; ni < NI; ++ni)
                    mma_tf32(acc[mi][ni], afr[mi], bfr[ni]);
        }

        __syncthreads();                       // all warps done reading stage s
        if (it + 2 < NT) issue_stage((it + 2) * BK, s);
        cp_commit();                           // one group per iter (may be empty)
        cp_wait<1>();                          // stage s^1 (tile it+1) landed raw
        if (it + 1 < NT) convert_stage(s ^ 1); // convert own elements in place
        __syncthreads();                       // publish converted stage s^1
    }

    // ---- epilogue (vectorized float2 stores; n0 is even, 8B-aligned) ----
    float*       Cb = Csel + (size_t)batch * strideC;
    const float* Rb = HAS_RES ? (res + (size_t)batch * strideR) : nullptr;
    #pragma unroll
    for (int mi = 0; mi < MI; ++mi) {
        #pragma unroll
        for (int ni = 0; ni < NI; ++ni) {
            int m0 = by * BM + wm * WM + mi * 16 + g;
            int n0 = blockIdx.x * BN + wn * WN + ni * 8 + tg * 2;
            #pragma unroll
            for (int h = 0; h < 2; ++h) {
                int m = m0 + h * 8;
                float v0 = acc[mi][ni][h * 2 + 0] * alpha;
                float v1 = acc[mi][ni][h * 2 + 1] * alpha;
                if (HAS_BIAS) { float bb = bsel[m]; v0 += bb; v1 += bb; }
                size_t off = (size_t)m * N + n0;
                if (HAS_RES) {
                    float2 rv = *reinterpret_cast<const float2*>(Rb + off);
                    v0 += rv.x; v1 += rv.y;
                }
                *reinterpret_cast<float2*>(Cb + off) = make_float2(v0, v1);
            }
        }
    }
}

// ---------------------------------------------------------------------------
// Row softmax over 256-wide rows: one warp per row (in-place safe).
// ---------------------------------------------------------------------------
__global__ void softmax256_kernel(const float* __restrict__ in, float* __restrict__ out, int nrows)
{
    int row  = (blockIdx.x * blockDim.x + threadIdx.x) >> 5;
    int lane = threadIdx.x & 31;
    if (row >= nrows) return;
    const float* r = in + (size_t)row * MMID_;
    float v[8];
    float mx = -INFINITY;
    #pragma unroll
    for (int i = 0; i < 8; ++i) { v[i] = r[lane + i * 32]; mx = fmaxf(mx, v[i]); }
    #pragma unroll
    for (int o = 16; o > 0; o >>= 1) mx = fmaxf(mx, __shfl_xor_sync(0xffffffffu, mx, o));
    float s = 0.f;
    #pragma unroll
    for (int i = 0; i < 8; ++i) { v[i] = expf(v[i] - mx); s += v[i]; }
    #pragma unroll
    for (int o = 16; o > 0; o >>= 1) s += __shfl_xor_sync(0xffffffffu, s, o);
    float inv = 1.f / s;
    float* w = out + (size_t)row * MMID_;
    #pragma unroll
    for (int i = 0; i < 8; ++i) w[lane + i * 32] = v[i] * inv;
}

// ---------------------------------------------------------------------------
extern "C" void kernel_launch(void* const* d_in, const int* in_sizes, int n_in,
                              void* d_out, int out_size)
{
    const float* x        = (const float*)d_in[0];  // [16,512,64,64]
    const float* W_state  = (const float*)d_in[1];  // [256,512]
    const float* b_state  = (const float*)d_in[2];  // [256]
    const float* W_proj   = (const float*)d_in[3];  // [256,512]
    const float* b_proj   = (const float*)d_in[4];  // [256]
    const float* W_extend = (const float*)d_in[5];  // [512,256]
    const float* b_extend = (const float*)d_in[6];  // [512]
    float* out = (float*)d_out;

    float *st, *pr, *at, *rs;
    cudaGetSymbolAddress((void**)&st, g_state);
    cudaGetSymbolAddress((void**)&pr, g_proj);
    cudaGetSymbolAddress((void**)&at, g_attn);
    cudaGetSymbolAddress((void**)&rs, g_rstate);

    const long long sX  = (long long)C_IN_ * HW_;
    const long long sM  = (long long)MMID_ * HW_;
    const long long sA  = (long long)MMID_ * MMID_;

    // dynamic smem: 2 stages * (A + B tile) * 4B
    const int SMEM_BIG    = 2 * (128 * 36 + 32 * 136) * 4;  // 71680 B
    const int SMEM_SCORES = 2 * (64 * 36 + 64 * 36) * 4;    // 36864 B

    auto kFused  = gemm_tf32_kernel<128,128,32,64,32,false,true ,false,true ,2>;
    auto kScores = gemm_tf32_kernel< 64, 64,32,32,32,true ,false,false,false,4>;
    auto kRstate = gemm_tf32_kernel<128,128,32,64,32,false,false,false,false,2>;
    auto kExtend = gemm_tf32_kernel<128,128,32,64,32,false,true ,true ,false,2>;

    cudaFuncSetAttribute(kFused,  cudaFuncAttributeMaxDynamicSharedMemorySize, SMEM_BIG);
    cudaFuncSetAttribute(kScores, cudaFuncAttributeMaxDynamicSharedMemorySize, SMEM_SCORES);
    cudaFuncSetAttribute(kRstate, cudaFuncAttributeMaxDynamicSharedMemorySize, SMEM_BIG);
    cudaFuncSetAttribute(kExtend, cudaFuncAttributeMaxDynamicSharedMemorySize, SMEM_BIG);

    // 1+2 fused) state = W_state @ x + b_state ; proj = W_proj @ x + b_proj
    kFused<<<dim3(HW_/128, 2 * (MMID_/128), NB_), 256, SMEM_BIG>>>(
            W_state, 0, x, sX, st, sM, b_state, nullptr, 0,
            W_proj, b_proj, pr,
            MMID_, HW_, C_IN_, 1.0f);

    // 3) scores = state @ proj^T / 64       [16,256,256]
    kScores<<<dim3(MMID_/64, MMID_/64, NB_), 128, SMEM_SCORES>>>(
            st, sM, pr, sM, at, sA, nullptr, nullptr, 0,
            nullptr, nullptr, nullptr,
            MMID_, MMID_, HW_, 1.0f / 64.0f);

    // 4) softmax over last dim (in place)
    softmax256_kernel<<<(NB_ * MMID_ * 32 + 127) / 128, 128>>>(at, at, NB_ * MMID_);

    // 5) rstate = attn @ proj               [16,256,4096]
    kRstate<<<dim3(HW_/128, MMID_/128, NB_), 256, SMEM_BIG>>>(
            at, sA, pr, sM, rs, sM, nullptr, nullptr, 0,
            nullptr, nullptr, nullptr,
            MMID_, HW_, MMID_, 1.0f);

    // 6) out = x + W_extend @ rstate + b_extend   [16,512,4096]
    kExtend<<<dim3(HW_/128, C_IN_/128, NB_), 256, SMEM_BIG>>>(
            W_extend, 0, rs, sM, out, sX, b_extend, x, sX,
            nullptr, nullptr, nullptr,
            C_IN_, HW_, MMID_, 1.0f);
}

// round 12
// speedup vs baseline: 1.2768x; 1.2768x over previous
#include <cuda_runtime.h>
#include <cstdint>
#include <math.h>

// Problem constants
#define HW_   4096
#define C_IN_ 512
#define MMID_ 256
#define NB_   16

// Scratch (device globals: allocation-free, graph-capturable)
__device__ float g_state [NB_ * MMID_ * HW_];   // 64 MB (tf32-prerounded)
__device__ float g_proj  [NB_ * MMID_ * HW_];   // 64 MB (tf32-prerounded)
__device__ float g_attn  [NB_ * MMID_ * MMID_]; //  4 MB (tf32-prerounded)
__device__ float g_rstate[NB_ * MMID_ * HW_];   // 64 MB (tf32-prerounded)
__device__ float g_wst   [MMID_ * C_IN_];       // rounded W_state
__device__ float g_wpr   [MMID_ * C_IN_];       // rounded W_proj
__device__ float g_wex   [C_IN_ * MMID_];       // rounded W_extend

__device__ __forceinline__ uint32_t f2tf32(float x) {
    uint32_t r;
    asm("cvt.rna.tf32.f32 %0, %1;" : "=r"(r) : "f"(x));
    return r;
}
__device__ __forceinline__ float f2tf32f(float x) {
    return __uint_as_float(f2tf32(x));
}

__device__ __forceinline__ void mma_tf32(float c[4], const uint32_t a[4], const uint32_t b[2]) {
    asm volatile(
        "mma.sync.aligned.m16n8k8.row.col.f32.tf32.tf32.f32 "
        "{%0,%1,%2,%3}, {%4,%5,%6,%7}, {%8,%9}, {%0,%1,%2,%3};"
        : "+f"(c[0]), "+f"(c[1]), "+f"(c[2]), "+f"(c[3])
        : "r"(a[0]), "r"(a[1]), "r"(a[2]), "r"(a[3]),
          "r"(b[0]), "r"(b[1]));
}

__device__ __forceinline__ void cp16(uint32_t smem_dst, const void* gsrc) {
    asm volatile("cp.async.cg.shared.global [%0], [%1], 16;\n"
                 :: "r"(smem_dst), "l"(gsrc));
}
__device__ __forceinline__ void cp_commit() {
    asm volatile("cp.async.commit_group;\n");
}
template<int N>
__device__ __forceinline__ void cp_wait() {
    asm volatile("cp.async.wait_group %0;\n" :: "n"(N));
}

// ---------------------------------------------------------------------------
// Batched tf32 GEMM, 2-stage cp.async double-buffered smem pipeline.
// CVT_A / CVT_B: apply cvt.rna.tf32 at fragment load. Operands produced by
// our own kernels are pre-rounded at the producer (idempotent cvt => values
// bit-identical to converting at load), so most mainloops run with zero cvt.
// ROUND_OUT: epilogue stores tf32-prerounded values (for intermediates).
//   TRANS_B == false : B is [K,N] row-major       (C = A*B)
//   TRANS_B == true  : B is [N,K] row-major       (C = A*B^T)
// DUAL == true: gridDim.y doubled; upper half of y-blocks uses {A2,bias2,C2}.
// ---------------------------------------------------------------------------
template<int BM, int BN, int BK, int WM, int WN,
         bool TRANS_B, bool HAS_BIAS, bool HAS_RES, bool DUAL,
         bool CVT_A, bool CVT_B, bool ROUND_OUT, int MINB>
__global__ void __launch_bounds__((BM / WM) * (BN / WN) * 32, MINB)
gemm_tf32_kernel(
    const float* __restrict__ A, long long strideA,
    const float* __restrict__ B, long long strideB,
    float*       __restrict__ Cout, long long strideC,
    const float* __restrict__ bias,
    const float* __restrict__ res, long long strideR,
    const float* __restrict__ A2,
    const float* __restrict__ bias2,
    float*       __restrict__ C2,
    int M, int N, int K, float alpha)
{
    constexpr int WARPS_M = BM / WM;
    constexpr int WARPS_N = BN / WN;
    constexpr int THREADS = WARPS_M * WARPS_N * 32;
    constexpr int MI = WM / 16;
    constexpr int NI = WN / 8;
    constexpr int LDA    = BK + 4;   // 36 : conflict-free fragment loads
    constexpr int LDB_NN = BN + 8;   // 136/72 : conflict-free fragment loads
    constexpr int B_ROWS = TRANS_B ? BN : BK;
    constexpr int B_LD   = TRANS_B ? LDA : LDB_NN;
    constexpr int A_ELEMS = BM * LDA;
    constexpr int B_ELEMS = B_ROWS * B_LD;
    constexpr int STAGE   = A_ELEMS + B_ELEMS;
    constexpr int A_F4  = (BM * BK / 4) / THREADS;
    constexpr int B_F4n = (BK * BN / 4) / THREADS;
    constexpr int B_F4t = (B_ROWS * BK / 4) / THREADS;
    static_assert((BM * BK / 4) % THREADS == 0, "");

    extern __shared__ float sm[];

    const int tid  = threadIdx.x;
    const int warp = tid >> 5;
    const int lane = tid & 31;
    const int wm   = warp / WARPS_N;
    const int wn   = warp % WARPS_N;
    const int g    = lane >> 2;
    const int tg   = lane & 3;
    const int batch = blockIdx.z;

    // ---- DUAL dispatch ----
    int by = blockIdx.y;
    const float* Asel = A;
    const float* bsel = bias;
    float*       Csel = Cout;
    if (DUAL) {
        const int halfY = gridDim.y >> 1;
        if (by >= halfY) { by -= halfY; Asel = A2; bsel = bias2; Csel = C2; }
    }

    const float* Ab = Asel + (size_t)batch * strideA + (size_t)by * BM * K;
    const float* Bb = B + (size_t)batch * strideB;

    // ---- async stage issue: gmem -> smem stage s (raw fp32 bits) ----
    auto issue_stage = [&](int k0, int s) {
        float* sa = sm + s * STAGE;
        float* sb = sa + A_ELEMS;
        #pragma unroll
        for (int i = 0; i < A_F4; ++i) {
            int idx = tid + i * THREADS;
            int row = idx / (BK / 4);
            int c4  = (idx % (BK / 4)) * 4;
            cp16((uint32_t)__cvta_generic_to_shared(&sa[row * LDA + c4]),
                 Ab + (size_t)row * K + k0 + c4);
        }
        if (!TRANS_B) {
            const float* Bp = Bb + (size_t)k0 * N + (size_t)blockIdx.x * BN;
            #pragma unroll
            for (int i = 0; i < B_F4n; ++i) {
                int idx = tid + i * THREADS;
                int row = idx / (BN / 4);
                int c4  = (idx % (BN / 4)) * 4;
                cp16((uint32_t)__cvta_generic_to_shared(&sb[row * LDB_NN + c4]),
                     Bp + (size_t)row * N + c4);
            }
        } else {
            const float* Bp = Bb + (size_t)blockIdx.x * BN * K + k0;
            #pragma unroll
            for (int i = 0; i < B_F4t; ++i) {
                int idx = tid + i * THREADS;
                int row = idx / (BK / 4);
                int c4  = (idx % (BK / 4)) * 4;
                cp16((uint32_t)__cvta_generic_to_shared(&sb[row * LDA + c4]),
                     Bp + (size_t)row * K + c4);
            }
        }
    };

    float acc[MI][NI][4];
    #pragma unroll
    for (int mi = 0; mi < MI; ++mi)
        #pragma unroll
        for (int ni = 0; ni < NI; ++ni)
            #pragma unroll
            for (int j = 0; j < 4; ++j) acc[mi][ni][j] = 0.f;

    const int NT = K / BK;   // always >= 2 for our shapes

    // ---- prologue: stage tiles 0 and 1 ----
    issue_stage(0, 0);  cp_commit();
    issue_stage(BK, 1); cp_commit();
    cp_wait<1>();        // stage 0 landed
    __syncthreads();

    for (int it = 0; it < NT; ++it) {
        const int s = it & 1;
        const uint32_t* sa = reinterpret_cast<const uint32_t*>(sm + s * STAGE);
        const uint32_t* sb = sa + A_ELEMS;

        // ---- compute on stage s: BK/8 k-steps of m16n8k8 ----
        #pragma unroll
        for (int ki = 0; ki < BK / 8; ++ki) {
            uint32_t afr[MI][4];
            uint32_t bfr[NI][2];
            #pragma unroll
            for (int mi = 0; mi < MI; ++mi) {
                int r = wm * WM + mi * 16;
                uint32_t u0 = sa[(r + g    ) * LDA + ki * 8 + tg    ];
                uint32_t u1 = sa[(r + 8 + g) * LDA + ki * 8 + tg    ];
                uint32_t u2 = sa[(r + g    ) * LDA + ki * 8 + 4 + tg];
                uint32_t u3 = sa[(r + 8 + g) * LDA + ki * 8 + 4 + tg];
                if (CVT_A) {
                    u0 = f2tf32(__uint_as_float(u0));
                    u1 = f2tf32(__uint_as_float(u1));
                    u2 = f2tf32(__uint_as_float(u2));
                    u3 = f2tf32(__uint_as_float(u3));
                }
                afr[mi][0] = u0; afr[mi][1] = u1; afr[mi][2] = u2; afr[mi][3] = u3;
            }
            #pragma unroll
            for (int ni = 0; ni < NI; ++ni) {
                int ncol = wn * WN + ni * 8 + g;
                uint32_t v0, v1;
                if (!TRANS_B) {
                    v0 = sb[(ki * 8 + tg    ) * LDB_NN + ncol];
                    v1 = sb[(ki * 8 + 4 + tg) * LDB_NN + ncol];
                } else {
                    v0 = sb[ncol * LDA + ki * 8 + tg    ];
                    v1 = sb[ncol * LDA + ki * 8 + 4 + tg];
                }
                if (CVT_B) {
                    v0 = f2tf32(__uint_as_float(v0));
                    v1 = f2tf32(__uint_as_float(v1));
                }
                bfr[ni][0] = v0; bfr[ni][1] = v1;
            }
            #pragma unroll
            for (int mi = 0; mi < MI; ++mi)
                #pragma unroll
                for (int ni = 0; ni < NI; ++ni)
                    mma_tf32(acc[mi][ni], afr[mi], bfr[ni]);
        }

        __syncthreads();                       // all warps done reading stage s
        if (it + 2 < NT) issue_stage((it + 2) * BK, s);
        cp_commit();                           // one group per iter (may be empty)
        cp_wait<1>();                          // stage s^1 (tile it+1) landed
        __syncthreads();                       // visible to all warps
    }

    // ---- epilogue (float2 stores; n0 is even -> 8B-aligned) ----
    float*       Cb = Csel + (size_t)batch * strideC;
    const float* Rb = HAS_RES ? (res + (size_t)batch * strideR) : nullptr;
    #pragma unroll
    for (int mi = 0; mi < MI; ++mi) {
        #pragma unroll
        for (int ni = 0; ni < NI; ++ni) {
            int m0 = by * BM + wm * WM + mi * 16 + g;
            int n0 = blockIdx.x * BN + wn * WN + ni * 8 + tg * 2;
            #pragma unroll
            for (int h = 0; h < 2; ++h) {
                int m = m0 + h * 8;
                float v0 = acc[mi][ni][h * 2 + 0] * alpha;
                float v1 = acc[mi][ni][h * 2 + 1] * alpha;
                if (HAS_BIAS) { float bb = bsel[m]; v0 += bb; v1 += bb; }
                size_t off = (size_t)m * N + n0;
                if (HAS_RES) {
                    float2 rv = *reinterpret_cast<const float2*>(Rb + off);
                    v0 += rv.x; v1 += rv.y;
                }
                if (ROUND_OUT) { v0 = f2tf32f(v0); v1 = f2tf32f(v1); }
                *reinterpret_cast<float2*>(Cb + off) = make_float2(v0, v1);
            }
        }
    }
}

// ---------------------------------------------------------------------------
// Row softmax over 256-wide rows: one warp per row; stores tf32-prerounded
// attn (bit-identical to rounding at the consumer's fragment load).
// ---------------------------------------------------------------------------
__global__ void softmax256_kernel(const float* __restrict__ in, float* __restrict__ out, int nrows)
{
    int row  = (blockIdx.x * blockDim.x + threadIdx.x) >> 5;
    int lane = threadIdx.x & 31;
    if (row >= nrows) return;
    const float* r = in + (size_t)row * MMID_;
    float v[8];
    float mx = -INFINITY;
    #pragma unroll
    for (int i = 0; i < 8; ++i) { v[i] = r[lane + i * 32]; mx = fmaxf(mx, v[i]); }
    #pragma unroll
    for (int o = 16; o > 0; o >>= 1) mx = fmaxf(mx, __shfl_xor_sync(0xffffffffu, mx, o));
    float s = 0.f;
    #pragma unroll
    for (int i = 0; i < 8; ++i) { v[i] = expf(v[i] - mx); s += v[i]; }
    #pragma unroll
    for (int o = 16; o > 0; o >>= 1) s += __shfl_xor_sync(0xffffffffu, s, o);
    float inv = 1.f / s;
    float* w = out + (size_t)row * MMID_;
    #pragma unroll
    for (int i = 0; i < 8; ++i) w[lane + i * 32] = f2tf32f(v[i] * inv);
}

// ---------------------------------------------------------------------------
// Pre-round the three weight tensors to tf32 in ONE launch (disjoint ranges).
// ---------------------------------------------------------------------------
__global__ void round_weights_kernel(const float* __restrict__ w1, float* __restrict__ o1, int n1,
                                     const float* __restrict__ w2, float* __restrict__ o2, int n2,
                                     const float* __restrict__ w3, float* __restrict__ o3, int n3)
{
    int i = blockIdx.x * blockDim.x + threadIdx.x;
    if (i < n1) o1[i] = f2tf32f(w1[i]);
    else if (i < n1 + n2) { int j = i - n1; o2[j] = f2tf32f(w2[j]); }
    else if (i < n1 + n2 + n3) { int j = i - n1 - n2; o3[j] = f2tf32f(w3[j]); }
}

// ---------------------------------------------------------------------------
extern "C" void kernel_launch(void* const* d_in, const int* in_sizes, int n_in,
                              void* d_out, int out_size)
{
    const float* x        = (const float*)d_in[0];  // [16,512,64,64]
    const float* W_state  = (const float*)d_in[1];  // [256,512]
    const float* b_state  = (const float*)d_in[2];  // [256]
    const float* W_proj   = (const float*)d_in[3];  // [256,512]
    const float* b_proj   = (const float*)d_in[4];  // [256]
    const float* W_extend = (const float*)d_in[5];  // [512,256]
    const float* b_extend = (const float*)d_in[6];  // [512]
    float* out = (float*)d_out;

    float *st, *pr, *at, *rs, *wst, *wpr, *wex;
    cudaGetSymbolAddress((void**)&st,  g_state);
    cudaGetSymbolAddress((void**)&pr,  g_proj);
    cudaGetSymbolAddress((void**)&at,  g_attn);
    cudaGetSymbolAddress((void**)&rs,  g_rstate);
    cudaGetSymbolAddress((void**)&wst, g_wst);
    cudaGetSymbolAddress((void**)&wpr, g_wpr);
    cudaGetSymbolAddress((void**)&wex, g_wex);

    const long long sX  = (long long)C_IN_ * HW_;
    const long long sM  = (long long)MMID_ * HW_;
    const long long sA  = (long long)MMID_ * MMID_;

    // dynamic smem: 2 stages * (A + B tile) * 4B
    const int SMEM_BIG    = 2 * (128 * 36 + 32 * 136) * 4;  // 71680 B
    const int SMEM_SCORES = 2 * (64 * 36 + 64 * 36) * 4;    // 36864 B

    // <BM,BN,BK,WM,WN,TRANS_B,BIAS,RES,DUAL,CVT_A,CVT_B,ROUND_OUT,MINB>
    auto kFused  = gemm_tf32_kernel<128,128,32,64,32,false,true ,false,true ,false,true ,true ,2>;
    auto kScores = gemm_tf32_kernel< 64, 64,32,32,32,true ,false,false,false,false,false,false,4>;
    auto kRstate = gemm_tf32_kernel<128,128,32,64,32,false,false,false,false,false,false,true ,2>;
    auto kExtend = gemm_tf32_kernel<128,128,32,64,32,false,true ,true ,false,false,false,false,2>;

    cudaFuncSetAttribute(kFused,  cudaFuncAttributeMaxDynamicSharedMemorySize, SMEM_BIG);
    cudaFuncSetAttribute(kScores, cudaFuncAttributeMaxDynamicSharedMemorySize, SMEM_SCORES);
    cudaFuncSetAttribute(kRstate, cudaFuncAttributeMaxDynamicSharedMemorySize, SMEM_BIG);
    cudaFuncSetAttribute(kExtend, cudaFuncAttributeMaxDynamicSharedMemorySize, SMEM_BIG);

    // 0) pre-round all weights to tf32 in one launch
    const int nW = 2 * MMID_ * C_IN_ + C_IN_ * MMID_;
    round_weights_kernel<<<(nW + 255)/256, 256>>>(
        W_state, wst, MMID_*C_IN_,
        W_proj,  wpr, MMID_*C_IN_,
        W_extend,wex, C_IN_*MMID_);

    // 1+2 fused) state/proj = W @ x + b  (outputs tf32-prerounded)
    kFused<<<dim3(HW_/128, 2 * (MMID_/128), NB_), 256, SMEM_BIG>>>(
            wst, 0, x, sX, st, sM, b_state, nullptr, 0,
            wpr, b_proj, pr,
            MMID_, HW_, C_IN_, 1.0f);

    // 3) scores = state @ proj^T / 64   (operands prerounded -> no cvt)
    kScores<<<dim3(MMID_/64, MMID_/64, NB_), 128, SMEM_SCORES>>>(
            st, sM, pr, sM, at, sA, nullptr, nullptr, 0,
            nullptr, nullptr, nullptr,
            MMID_, MMID_, HW_, 1.0f / 64.0f);

    // 4) softmax (stores prerounded attn)
    softmax256_kernel<<<(NB_ * MMID_ * 32 + 127) / 128, 128>>>(at, at, NB_ * MMID_);

    // 5) rstate = attn @ proj  (no cvt; output prerounded)
    kRstate<<<dim3(HW_/128, MMID_/128, NB_), 256, SMEM_BIG>>>(
            at, sA, pr, sM, rs, sM, nullptr, nullptr, 0,
            nullptr, nullptr, nullptr,
            MMID_, HW_, MMID_, 1.0f);

    // 6) out = x + W_extend @ rstate + b_extend  (no cvt; exact fp32 out)
    kExtend<<<dim3(HW_/128, C_IN_/128, NB_), 256, SMEM_BIG>>>(
            wex, 0, rs, sM, out, sX, b_extend, x, sX,
            nullptr, nullptr, nullptr,
            C_IN_, HW_, MMID_, 1.0f);
}